// round 3
// baseline (speedup 1.0000x reference)
#include <cuda_runtime.h>

#define NN   50000
#define NE   1600000
#define NR   8
#define KC   1152        // NR*128 + 128 (relation means ++ self term)
#define CAP  16384       // max compacted "needed" nodes (expected ~8.4K)
#define NP   256
#define DOUT 64

typedef unsigned long long ull;

// packed fp32x2 FMA (sm_103a): d = a*b + d elementwise on {lo,hi} pairs
#define FMA2(d, a, b) asm("fma.rn.f32x2 %0, %1, %2, %0;" : "+l"(d) : "l"(a), "l"(b))
#define UNPK2(lo, hi, d) asm("mov.b64 {%0, %1}, %2;" : "=f"(lo), "=f"(hi) : "l"(d))

// ---- scratch (device globals: no allocation allowed in kernel_launch) ----
__device__ int   g_pmap[NN];
__device__ int   g_nf[NN];
__device__ int   g_cid[NN];
__device__ int   g_nodes[CAP];
__device__ int   g_counter;
__device__ int   g_head[NR * NN];
__device__ int   g_next[NE];
__device__ float g_C[(size_t)CAP * KC];
__device__ float g_h[(size_t)CAP * 128];
__device__ float g_part[NP * DOUT];
__device__ float g_wp[NP];

// ---------------------------------------------------------------- init
__global__ void k_init() {
    int i = blockIdx.x * blockDim.x + threadIdx.x;
    if (i < NR * NN) g_head[i] = -1;
    if (i < NN) { g_pmap[i] = 0; g_nf[i] = 0; }
    if (i == 0) g_counter = 0;
}

__global__ void k_mark_pool(const int* __restrict__ pool) {
    int p = pool[threadIdx.x];
    g_pmap[p] = 1;
    g_nf[p]   = 1;
}

__global__ void k_mark_src(const int* __restrict__ ei) {
    int e = blockIdx.x * blockDim.x + threadIdx.x;
    if (e >= NE) return;
    int dst = ei[NE + e];
    if (g_pmap[dst]) g_nf[ei[e]] = 1;
}

__global__ void k_compact() {
    int v = blockIdx.x * blockDim.x + threadIdx.x;
    if (v >= NN) return;
    if (g_nf[v]) {
        int c = atomicAdd(&g_counter, 1);
        if (c < CAP) { g_cid[v] = c; g_nodes[c] = v; }
    }
}

__global__ void k_build(const int* __restrict__ ei, const int* __restrict__ et) {
    int e = blockIdx.x * blockDim.x + threadIdx.x;
    if (e >= NE) return;
    int dst = ei[NE + e];
    if (!g_nf[dst]) return;
    int r = et[e];
    g_next[e] = atomicExch(&g_head[r * NN + dst], e);
}

// ------------------------------------------------- layer-1 aggregation
__global__ void k_agg1(const float* __restrict__ x, const int* __restrict__ ei) {
    const float4* x4 = (const float4*)x;
    int wid   = (blockIdx.x * blockDim.x + threadIdx.x) >> 5;
    int lane  = threadIdx.x & 31;
    int nwarp = (gridDim.x * blockDim.x) >> 5;
    int cnt   = min(g_counter, CAP);
    int ntask = cnt * 9;
    for (int t = wid; t < ntask; t += nwarp) {
        int i = t / 9;
        int r = t - i * 9;
        int v = g_nodes[i];
        float4 acc = make_float4(0.f, 0.f, 0.f, 0.f);
        if (r == 8) {
            acc = x4[v * 32 + lane];
        } else {
            int ptr = g_head[r * NN + v];
            int c = 0;
            while (ptr >= 0) {
                int src = ei[ptr];
                float4 xv = x4[src * 32 + lane];
                acc.x += xv.x; acc.y += xv.y; acc.z += xv.z; acc.w += xv.w;
                c++;
                ptr = g_next[ptr];
            }
            if (c > 1) {
                float s = 1.0f / (float)c;
                acc.x *= s; acc.y *= s; acc.z *= s; acc.w *= s;
            }
        }
        *(float4*)&g_C[(size_t)i * KC + r * 128 + lane * 4] = acc;
    }
}

// ------------------------------------------------- layer-1 GEMM + relu
// h = relu(C @ [W1;root1] + b1). M=n_needed, N=128, K=1152.
// 256 threads, 64x128 block tile, 4x8 microtile (acc as 2 row-pairs x 8 cols).
// FFMA2 everywhere; B staged pre-duplicated {w,w} so packed operands come
// straight from LDS (no mov.b64 in the inner loop).
__global__ void __launch_bounds__(256) k_gemm1(const float* __restrict__ W1,
                                               const float* __restrict__ root1,
                                               const float* __restrict__ b1) {
    __shared__ __align__(16) float Cs[32 * 66];     // [k][row], stride 66
    __shared__ __align__(16) float Ws2[32 * 256];   // [k][col duplicated x2]
    int cnt  = min(g_counter, CAP);
    int row0 = blockIdx.x * 64;
    if (row0 >= cnt) return;
    int t  = threadIdx.x;
    int cg = t & 15;   // cols cg*8 .. cg*8+7
    int rg = t >> 4;   // rows rg*4 .. rg*4+3

    ull acc[2][8];     // [row-pair][col]
#pragma unroll
    for (int i = 0; i < 2; i++)
#pragma unroll
        for (int j = 0; j < 8; j++) acc[i][j] = 0ull;

    for (int kc = 0; kc < KC / 32; kc++) {
        // stage C tile (64 rows x 32 k), transposed to Cs[k][row]
#pragma unroll
        for (int q = 0; q < 2; q++) {
            int idx = t + q * 256;          // 0..511 float4 reads
            int row = idx >> 3, k4 = idx & 7;
            int gr = row0 + row;
            float4 v = (gr < cnt) ? *(const float4*)&g_C[(size_t)gr * KC + kc * 32 + k4 * 4]
                                  : make_float4(0.f, 0.f, 0.f, 0.f);
            Cs[(k4 * 4 + 0) * 66 + row] = v.x;
            Cs[(k4 * 4 + 1) * 66 + row] = v.y;
            Cs[(k4 * 4 + 2) * 66 + row] = v.z;
            Cs[(k4 * 4 + 3) * 66 + row] = v.w;
        }
        // stage W slab (32 k x 128 cols), duplicated to pairs
#pragma unroll
        for (int q = 0; q < 4; q++) {
            int idx = t + q * 256;          // 0..1023 source float4s
            int k = idx >> 5, c4 = idx & 31;
            int gk = kc * 32 + k;
            float4 wv = (gk < 1024) ? *(const float4*)&W1[gk * 128 + c4 * 4]
                                    : *(const float4*)&root1[(gk - 1024) * 128 + c4 * 4];
            float4 d0 = make_float4(wv.x, wv.x, wv.y, wv.y);
            float4 d1 = make_float4(wv.z, wv.z, wv.w, wv.w);
            *(float4*)&Ws2[k * 256 + c4 * 8]     = d0;
            *(float4*)&Ws2[k * 256 + c4 * 8 + 4] = d1;
        }
        __syncthreads();
#pragma unroll 4
        for (int k = 0; k < 32; k++) {
            const ull* ap = (const ull*)&Cs[k * 66 + rg * 4];
            ull a0 = ap[0], a1 = ap[1];
            const ulonglong2* bp = (const ulonglong2*)&Ws2[k * 256 + cg * 16];
            ulonglong2 B0 = bp[0], B1 = bp[1], B2 = bp[2], B3 = bp[3];
            FMA2(acc[0][0], a0, B0.x); FMA2(acc[0][1], a0, B0.y);
            FMA2(acc[0][2], a0, B1.x); FMA2(acc[0][3], a0, B1.y);
            FMA2(acc[0][4], a0, B2.x); FMA2(acc[0][5], a0, B2.y);
            FMA2(acc[0][6], a0, B3.x); FMA2(acc[0][7], a0, B3.y);
            FMA2(acc[1][0], a1, B0.x); FMA2(acc[1][1], a1, B0.y);
            FMA2(acc[1][2], a1, B1.x); FMA2(acc[1][3], a1, B1.y);
            FMA2(acc[1][4], a1, B2.x); FMA2(acc[1][5], a1, B2.y);
            FMA2(acc[1][6], a1, B3.x); FMA2(acc[1][7], a1, B3.y);
        }
        __syncthreads();
    }

    // epilogue: unpack, +bias, relu, store
    float4 bb0 = *(const float4*)&b1[cg * 8];
    float4 bb1 = *(const float4*)&b1[cg * 8 + 4];
    float bv[8] = {bb0.x, bb0.y, bb0.z, bb0.w, bb1.x, bb1.y, bb1.z, bb1.w};
#pragma unroll
    for (int rp = 0; rp < 2; rp++) {
        float lo[8], hi[8];
#pragma unroll
        for (int j = 0; j < 8; j++) UNPK2(lo[j], hi[j], acc[rp][j]);
        int r_lo = row0 + rg * 4 + rp * 2;
        int r_hi = r_lo + 1;
        if (r_lo < cnt) {
            float4 o0, o1;
            o0.x = fmaxf(lo[0] + bv[0], 0.f); o0.y = fmaxf(lo[1] + bv[1], 0.f);
            o0.z = fmaxf(lo[2] + bv[2], 0.f); o0.w = fmaxf(lo[3] + bv[3], 0.f);
            o1.x = fmaxf(lo[4] + bv[4], 0.f); o1.y = fmaxf(lo[5] + bv[5], 0.f);
            o1.z = fmaxf(lo[6] + bv[6], 0.f); o1.w = fmaxf(lo[7] + bv[7], 0.f);
            *(float4*)&g_h[(size_t)r_lo * 128 + cg * 8]     = o0;
            *(float4*)&g_h[(size_t)r_lo * 128 + cg * 8 + 4] = o1;
        }
        if (r_hi < cnt) {
            float4 o0, o1;
            o0.x = fmaxf(hi[0] + bv[0], 0.f); o0.y = fmaxf(hi[1] + bv[1], 0.f);
            o0.z = fmaxf(hi[2] + bv[2], 0.f); o0.w = fmaxf(hi[3] + bv[3], 0.f);
            o1.x = fmaxf(hi[4] + bv[4], 0.f); o1.y = fmaxf(hi[5] + bv[5], 0.f);
            o1.z = fmaxf(hi[6] + bv[6], 0.f); o1.w = fmaxf(hi[7] + bv[7], 0.f);
            *(float4*)&g_h[(size_t)r_hi * 128 + cg * 8]     = o0;
            *(float4*)&g_h[(size_t)r_hi * 128 + cg * 8 + 4] = o1;
        }
    }
}

// -------------------------------- layer-2 (256 pooled rows) + weighting
__global__ void __launch_bounds__(256) k_pool(const float* __restrict__ x,
                                              const int* __restrict__ pool,
                                              const int* __restrict__ ei,
                                              const float* __restrict__ W2,
                                              const float* __restrict__ root2,
                                              const float* __restrict__ b2) {
    __shared__ float cs[KC];
    __shared__ float red[256];
    const float4* h4 = (const float4*)g_h;
    int p = pool[blockIdx.x];
    int t = threadIdx.x;
    int lane = t & 31, w = t >> 5;   // 8 warps == 8 relations

    {
        int r = w;
        int ptr = g_head[r * NN + p];
        int c = 0;
        float4 acc = make_float4(0.f, 0.f, 0.f, 0.f);
        while (ptr >= 0) {
            int src = ei[ptr];
            int ci = g_cid[src];
            float4 hv = h4[ci * 32 + lane];
            acc.x += hv.x; acc.y += hv.y; acc.z += hv.z; acc.w += hv.w;
            c++;
            ptr = g_next[ptr];
        }
        if (c > 1) {
            float s = 1.0f / (float)c;
            acc.x *= s; acc.y *= s; acc.z *= s; acc.w *= s;
        }
        *(float4*)&cs[r * 128 + lane * 4] = acc;
    }
    if (t < 128) {
        int cp = g_cid[p];
        cs[1024 + t] = g_h[(size_t)cp * 128 + t];
    }
    __syncthreads();

    int j = t & 63, q = t >> 6;   // 4-way K split
    float s = 0.f;
    int k0 = q * 288;
#pragma unroll 4
    for (int k = k0; k < k0 + 288; k++) {
        float wv = (k < 1024) ? W2[k * 64 + j] : root2[(k - 1024) * 64 + j];
        s += cs[k] * wv;
    }
    red[t] = s;
    __syncthreads();
    if (t < 64) {
        float o = red[t] + red[t + 64] + red[t + 128] + red[t + 192] + b2[j];
        float wp = 4.f * x[p * 128 + 0] + x[p * 128 + 1] + 2.f * x[p * 128 + 2];
        g_part[blockIdx.x * 64 + j] = o * wp;
        if (j == 0) g_wp[blockIdx.x] = wp;
    }
}

// fixed-order final reduction (deterministic)
__global__ void k_final(float* __restrict__ out) {
    int j = threadIdx.x;   // 64
    float acc = 0.f;
    for (int i = 0; i < NP; i++) acc += g_part[i * 64 + j];
    float ws = 0.f;
    for (int i = 0; i < NP; i++) ws += g_wp[i];
    out[j] = acc / (ws + 1e-9f);
}

// ---------------------------------------------------------------- launch
extern "C" void kernel_launch(void* const* d_in, const int* in_sizes, int n_in,
                              void* d_out, int out_size) {
    const float* x     = (const float*)d_in[0];
    const int*   ei    = (const int*)  d_in[1];   // [2, NE]: src row 0, dst row 1
    const int*   et    = (const int*)  d_in[2];
    const int*   pool  = (const int*)  d_in[3];
    const float* W1    = (const float*)d_in[4];
    const float* root1 = (const float*)d_in[5];
    const float* b1    = (const float*)d_in[6];
    const float* W2    = (const float*)d_in[7];
    const float* root2 = (const float*)d_in[8];
    const float* b2    = (const float*)d_in[9];
    float* out = (float*)d_out;
    (void)in_sizes; (void)n_in; (void)out_size;

    k_init     <<<(NR * NN + 255) / 256, 256>>>();
    k_mark_pool<<<1, NP>>>(pool);
    k_mark_src <<<(NE + 255) / 256, 256>>>(ei);
    k_compact  <<<(NN + 255) / 256, 256>>>();
    k_build    <<<(NE + 255) / 256, 256>>>(ei, et);
    k_agg1     <<<1024, 256>>>(x, ei);
    k_gemm1    <<<CAP / 64, 256>>>(W1, root1, b1);
    k_pool     <<<NP, 256>>>(x, pool, ei, W2, root2, b2);
    k_final    <<<1, 64>>>(out);
}

// round 4
// speedup vs baseline: 2.2277x; 2.2277x over previous
#include <cuda_runtime.h>

#define NN   50000
#define NE   1600000
#define NR   8
#define KC   1152        // NR*128 + 128 (relation means ++ self term)
#define CAP  16384       // max compacted "needed" nodes (expected ~8.4K)
#define NP   256
#define DOUT 64

// ---- scratch (device globals: no allocation allowed in kernel_launch) ----
__device__ int   g_pmap[NN];
__device__ int   g_nf[NN];
__device__ int   g_cid[NN];
__device__ int   g_nodes[CAP];
__device__ int   g_counter;
__device__ int   g_head[NR * NN];
__device__ int   g_next[NE];
__device__ float g_C[(size_t)CAP * KC];
__device__ float g_h[(size_t)CAP * 128];
__device__ float g_part[NP * DOUT];
__device__ float g_wp[NP];

// ---------------------------------------------------------------- init
__global__ void k_init() {
    int i = blockIdx.x * blockDim.x + threadIdx.x;
    if (i < NR * NN) g_head[i] = -1;
    if (i < NN) { g_pmap[i] = 0; g_nf[i] = 0; }
    if (i == 0) g_counter = 0;
}

__global__ void k_mark_pool(const int* __restrict__ pool) {
    int p = pool[threadIdx.x];
    g_pmap[p] = 1;
    g_nf[p]   = 1;
}

__global__ void k_mark_src(const int* __restrict__ ei) {
    int e = blockIdx.x * blockDim.x + threadIdx.x;
    if (e >= NE) return;
    int dst = ei[NE + e];
    if (g_pmap[dst]) g_nf[ei[e]] = 1;
}

__global__ void k_compact() {
    int v = blockIdx.x * blockDim.x + threadIdx.x;
    if (v >= NN) return;
    if (g_nf[v]) {
        int c = atomicAdd(&g_counter, 1);
        if (c < CAP) { g_cid[v] = c; g_nodes[c] = v; }
    }
}

__global__ void k_build(const int* __restrict__ ei, const int* __restrict__ et) {
    int e = blockIdx.x * blockDim.x + threadIdx.x;
    if (e >= NE) return;
    int dst = ei[NE + e];
    if (!g_nf[dst]) return;
    int r = et[e];
    g_next[e] = atomicExch(&g_head[r * NN + dst], e);
}

// ------------------------------------------------- layer-1 aggregation
__global__ void k_agg1(const float* __restrict__ x, const int* __restrict__ ei) {
    const float4* x4 = (const float4*)x;
    int wid   = (blockIdx.x * blockDim.x + threadIdx.x) >> 5;
    int lane  = threadIdx.x & 31;
    int nwarp = (gridDim.x * blockDim.x) >> 5;
    int cnt   = min(g_counter, CAP);
    int ntask = cnt * 9;
    for (int t = wid; t < ntask; t += nwarp) {
        int i = t / 9;
        int r = t - i * 9;
        int v = g_nodes[i];
        float4 acc = make_float4(0.f, 0.f, 0.f, 0.f);
        if (r == 8) {
            acc = x4[v * 32 + lane];
        } else {
            int ptr = g_head[r * NN + v];
            int c = 0;
            while (ptr >= 0) {
                int src = ei[ptr];
                float4 xv = x4[src * 32 + lane];
                acc.x += xv.x; acc.y += xv.y; acc.z += xv.z; acc.w += xv.w;
                c++;
                ptr = g_next[ptr];
            }
            if (c > 1) {
                float s = 1.0f / (float)c;
                acc.x *= s; acc.y *= s; acc.z *= s; acc.w *= s;
            }
        }
        *(float4*)&g_C[(size_t)i * KC + r * 128 + lane * 4] = acc;
    }
}

// ------------------------------------------------- layer-1 GEMM + relu
// h = relu(C @ [W1;root1] + b1). M=n_needed, N=128, K=1152.
// 256 threads, 64x128 block tile, 8x4 microtile, plain FFMA.
// A (rows) is warp-broadcast from Cs; B is one float4 per thread per k.
__global__ void __launch_bounds__(256) k_gemm1(const float* __restrict__ W1,
                                               const float* __restrict__ root1,
                                               const float* __restrict__ b1) {
    __shared__ __align__(16) float Cs[32 * 68];    // [k][row], stride 68
    __shared__ __align__(16) float Ws[32 * 128];   // [k][col]
    int cnt  = min(g_counter, CAP);
    int row0 = blockIdx.x * 64;
    if (row0 >= cnt) return;
    int t  = threadIdx.x;
    int cg = t & 31;   // cols cg*4 .. cg*4+3
    int rg = t >> 5;   // rows rg*8 .. rg*8+7

    float acc[8][4];
#pragma unroll
    for (int i = 0; i < 8; i++)
#pragma unroll
        for (int j = 0; j < 4; j++) acc[i][j] = 0.f;

    for (int kc = 0; kc < KC / 32; kc++) {
        // stage C tile (64 rows x 32 k), transposed to Cs[k][row]
#pragma unroll
        for (int q = 0; q < 2; q++) {
            int idx = t + q * 256;          // 0..511 float4 reads
            int row = idx >> 3, k4 = idx & 7;
            int gr = row0 + row;
            float4 v = (gr < cnt) ? *(const float4*)&g_C[(size_t)gr * KC + kc * 32 + k4 * 4]
                                  : make_float4(0.f, 0.f, 0.f, 0.f);
            Cs[(k4 * 4 + 0) * 68 + row] = v.x;
            Cs[(k4 * 4 + 1) * 68 + row] = v.y;
            Cs[(k4 * 4 + 2) * 68 + row] = v.z;
            Cs[(k4 * 4 + 3) * 68 + row] = v.w;
        }
        // stage W slab (32 k x 128 cols)
#pragma unroll
        for (int q = 0; q < 4; q++) {
            int idx = t + q * 256;          // float4 index
            int k = idx >> 5, c4 = idx & 31;
            int gk = kc * 32 + k;
            float4 wv = (gk < 1024) ? *(const float4*)&W1[gk * 128 + c4 * 4]
                                    : *(const float4*)&root1[(gk - 1024) * 128 + c4 * 4];
            *(float4*)&Ws[k * 128 + c4 * 4] = wv;
        }
        __syncthreads();
#pragma unroll 8
        for (int k = 0; k < 32; k++) {
            float4 b4 = *(const float4*)&Ws[k * 128 + cg * 4];
            float4 a0 = *(const float4*)&Cs[k * 68 + rg * 8];
            float4 a1 = *(const float4*)&Cs[k * 68 + rg * 8 + 4];
            float a_[8] = {a0.x, a0.y, a0.z, a0.w, a1.x, a1.y, a1.z, a1.w};
            float b_[4] = {b4.x, b4.y, b4.z, b4.w};
#pragma unroll
            for (int i = 0; i < 8; i++)
#pragma unroll
                for (int j = 0; j < 4; j++) acc[i][j] += a_[i] * b_[j];
        }
        __syncthreads();
    }

    float4 bb = *(const float4*)&b1[cg * 4];
    float bv[4] = {bb.x, bb.y, bb.z, bb.w};
#pragma unroll
    for (int i = 0; i < 8; i++) {
        int gr = row0 + rg * 8 + i;
        if (gr < cnt) {
            float4 o;
            o.x = fmaxf(acc[i][0] + bv[0], 0.f);
            o.y = fmaxf(acc[i][1] + bv[1], 0.f);
            o.z = fmaxf(acc[i][2] + bv[2], 0.f);
            o.w = fmaxf(acc[i][3] + bv[3], 0.f);
            *(float4*)&g_h[(size_t)gr * 128 + cg * 4] = o;
        }
    }
}

// -------------------------------- layer-2 (256 pooled rows) + weighting
__global__ void __launch_bounds__(256) k_pool(const float* __restrict__ x,
                                              const int* __restrict__ pool,
                                              const int* __restrict__ ei,
                                              const float* __restrict__ W2,
                                              const float* __restrict__ root2,
                                              const float* __restrict__ b2) {
    __shared__ float cs[KC];
    __shared__ float red[256];
    const float4* h4 = (const float4*)g_h;
    int p = pool[blockIdx.x];
    int t = threadIdx.x;
    int lane = t & 31, w = t >> 5;   // 8 warps == 8 relations

    {
        int r = w;
        int ptr = g_head[r * NN + p];
        int c = 0;
        float4 acc = make_float4(0.f, 0.f, 0.f, 0.f);
        while (ptr >= 0) {
            int src = ei[ptr];
            int ci = g_cid[src];
            float4 hv = h4[ci * 32 + lane];
            acc.x += hv.x; acc.y += hv.y; acc.z += hv.z; acc.w += hv.w;
            c++;
            ptr = g_next[ptr];
        }
        if (c > 1) {
            float s = 1.0f / (float)c;
            acc.x *= s; acc.y *= s; acc.z *= s; acc.w *= s;
        }
        *(float4*)&cs[r * 128 + lane * 4] = acc;
    }
    if (t < 128) {
        int cp = g_cid[p];
        cs[1024 + t] = g_h[(size_t)cp * 128 + t];
    }
    __syncthreads();

    int j = t & 63, q = t >> 6;   // 4-way K split
    float s = 0.f;
    int k0 = q * 288;
#pragma unroll 4
    for (int k = k0; k < k0 + 288; k++) {
        float wv = (k < 1024) ? W2[k * 64 + j] : root2[(k - 1024) * 64 + j];
        s += cs[k] * wv;
    }
    red[t] = s;
    __syncthreads();
    if (t < 64) {
        float o = red[t] + red[t + 64] + red[t + 128] + red[t + 192] + b2[j];
        float wp = 4.f * x[p * 128 + 0] + x[p * 128 + 1] + 2.f * x[p * 128 + 2];
        g_part[blockIdx.x * 64 + j] = o * wp;
        if (j == 0) g_wp[blockIdx.x] = wp;
    }
}

// fixed-order final reduction (deterministic)
__global__ void k_final(float* __restrict__ out) {
    int j = threadIdx.x;   // 64
    float acc = 0.f;
    for (int i = 0; i < NP; i++) acc += g_part[i * 64 + j];
    float ws = 0.f;
    for (int i = 0; i < NP; i++) ws += g_wp[i];
    out[j] = acc / (ws + 1e-9f);
}

// ---------------------------------------------------------------- launch
extern "C" void kernel_launch(void* const* d_in, const int* in_sizes, int n_in,
                              void* d_out, int out_size) {
    const float* x     = (const float*)d_in[0];
    const int*   ei    = (const int*)  d_in[1];   // [2, NE]: src row 0, dst row 1
    const int*   et    = (const int*)  d_in[2];
    const int*   pool  = (const int*)  d_in[3];
    const float* W1    = (const float*)d_in[4];
    const float* root1 = (const float*)d_in[5];
    const float* b1    = (const float*)d_in[6];
    const float* W2    = (const float*)d_in[7];
    const float* root2 = (const float*)d_in[8];
    const float* b2    = (const float*)d_in[9];
    float* out = (float*)d_out;
    (void)in_sizes; (void)n_in; (void)out_size;

    k_init     <<<(NR * NN + 255) / 256, 256>>>();
    k_mark_pool<<<1, NP>>>(pool);
    k_mark_src <<<(NE + 255) / 256, 256>>>(ei);
    k_compact  <<<(NN + 255) / 256, 256>>>();
    k_build    <<<(NE + 255) / 256, 256>>>(ei, et);
    k_agg1     <<<2048, 256>>>(x, ei);
    k_gemm1    <<<CAP / 64, 256>>>(W1, root1, b1);
    k_pool     <<<NP, 256>>>(x, pool, ei, W2, root2, b2);
    k_final    <<<1, 64>>>(out);
}

// round 6
// speedup vs baseline: 2.9179x; 1.3098x over previous
#include <cuda_runtime.h>
#include <cuda_bf16.h>

#define NN   50000
#define NE   1600000
#define NR   8
#define KC   1152        // NR*128 + 128
#define CAP  16384
#define NP   256
#define DOUT 64

// ---- scratch ----
__device__ int   g_pmap[NN];
__device__ int   g_nf[NN];
__device__ int   g_cid[NN];
__device__ int   g_nodes[CAP];
__device__ int   g_counter;
__device__ int   g_head[NR * NN];
__device__ int   g_next[NE];
__device__ __align__(16) __nv_bfloat16 g_Ahi[(size_t)CAP * KC];
__device__ __align__(16) __nv_bfloat16 g_Alo[(size_t)CAP * KC];
__device__ __align__(16) __nv_bfloat16 g_Bhi[128 * KC];   // [outcol h][k]
__device__ __align__(16) __nv_bfloat16 g_Blo[128 * KC];
__device__ float g_h[(size_t)CAP * 128];
__device__ float g_part[NP * DOUT];
__device__ float g_wp[NP];

static __device__ __forceinline__ void split2(float v, __nv_bfloat16& hi, __nv_bfloat16& lo) {
    hi = __float2bfloat16_rn(v);
    lo = __float2bfloat16_rn(v - __bfloat162float(hi));
}

// warp mma m16n8k16 bf16 -> f32 accum (baseline PTX, compiles to HMMA on sm_103)
#define MMA16816(c, a, b) \
    asm volatile("mma.sync.aligned.m16n8k16.row.col.f32.bf16.bf16.f32 " \
                 "{%0,%1,%2,%3},{%4,%5,%6,%7},{%8,%9},{%0,%1,%2,%3};" \
                 : "+f"((c)[0]), "+f"((c)[1]), "+f"((c)[2]), "+f"((c)[3]) \
                 : "r"((a)[0]), "r"((a)[1]), "r"((a)[2]), "r"((a)[3]), \
                   "r"((b)[0]), "r"((b)[1]))

// ---------------------------------------------------------------- init
__global__ void k_init() {
    int i = blockIdx.x * blockDim.x + threadIdx.x;
    if (i < NR * NN) g_head[i] = -1;
    if (i < NN) { g_pmap[i] = 0; g_nf[i] = 0; }
    if (i == 0) g_counter = 0;
}

__global__ void k_mark_pool(const int* __restrict__ pool) {
    int p = pool[threadIdx.x];
    g_pmap[p] = 1;
    g_nf[p]   = 1;
}

__global__ void k_mark_src(const int* __restrict__ ei) {
    int e = blockIdx.x * blockDim.x + threadIdx.x;
    if (e >= NE) return;
    int dst = ei[NE + e];
    if (g_pmap[dst]) g_nf[ei[e]] = 1;
}

__global__ void k_compact() {
    int v = blockIdx.x * blockDim.x + threadIdx.x;
    if (v >= NN) return;
    if (g_nf[v]) {
        int c = atomicAdd(&g_counter, 1);
        if (c < CAP) { g_cid[v] = c; g_nodes[c] = v; }
    }
}

__global__ void k_build(const int* __restrict__ ei, const int* __restrict__ et) {
    int e = blockIdx.x * blockDim.x + threadIdx.x;
    if (e >= NE) return;
    int dst = ei[NE + e];
    if (!g_nf[dst]) return;
    int r = et[e];
    g_next[e] = atomicExch(&g_head[r * NN + dst], e);
}

// weight split: B[h][k] = (k<1024 ? W1[k*128+h] : root1[(k-1024)*128+h]) -> bf16 hi/lo
__global__ void k_wsplit(const float* __restrict__ W1, const float* __restrict__ root1) {
    int idx = blockIdx.x * blockDim.x + threadIdx.x;   // 128*1152
    if (idx >= 128 * KC) return;
    int h = idx / KC, k = idx - h * KC;
    float w = (k < 1024) ? W1[k * 128 + h] : root1[(k - 1024) * 128 + h];
    __nv_bfloat16 hi, lo;
    split2(w, hi, lo);
    g_Bhi[idx] = hi;
    g_Blo[idx] = lo;
}

// ------------------------------------------------- layer-1 aggregation
// writes bf16 hi/lo planes of C (relation means ++ self row)
__global__ void k_agg1(const float* __restrict__ x, const int* __restrict__ ei) {
    const float4* x4 = (const float4*)x;
    int wid   = (blockIdx.x * blockDim.x + threadIdx.x) >> 5;
    int lane  = threadIdx.x & 31;
    int nwarp = (gridDim.x * blockDim.x) >> 5;
    int cnt   = min(g_counter, CAP);
    int ntask = cnt * 9;
    for (int t = wid; t < ntask; t += nwarp) {
        int i = t / 9;
        int r = t - i * 9;
        int v = g_nodes[i];
        float4 acc = make_float4(0.f, 0.f, 0.f, 0.f);
        if (r == 8) {
            acc = x4[v * 32 + lane];
        } else {
            int ptr = g_head[r * NN + v];
            int c = 0;
            while (ptr >= 0) {
                int src = ei[ptr];
                float4 xv = x4[src * 32 + lane];
                acc.x += xv.x; acc.y += xv.y; acc.z += xv.z; acc.w += xv.w;
                c++;
                ptr = g_next[ptr];
            }
            if (c > 1) {
                float s = 1.0f / (float)c;
                acc.x *= s; acc.y *= s; acc.z *= s; acc.w *= s;
            }
        }
        __nv_bfloat16 h[4], l[4];
        split2(acc.x, h[0], l[0]);
        split2(acc.y, h[1], l[1]);
        split2(acc.z, h[2], l[2]);
        split2(acc.w, h[3], l[3]);
        size_t off = (size_t)i * KC + r * 128 + lane * 4;
        *(uint2*)&g_Ahi[off] = *(uint2*)h;
        *(uint2*)&g_Alo[off] = *(uint2*)l;
    }
}

// ------------------------------------------------- layer-1 GEMM (warp HMMA)
// h = relu(C @ B^T + b1). M=cnt (<=CAP), N=128, K=1152.
// Block 64x128, 8 warps (2m x 4n), warp tile 32x32.
// bf16 2-way split: D = Ahi*Bhi + Alo*Bhi + Ahi*Blo (fp32 accum).
#define SA 40   // smem row stride in bf16 (conflict-free fragment pattern)
__global__ void __launch_bounds__(256) k_gemm1h(const float* __restrict__ b1) {
    __shared__ __align__(16) __nv_bfloat16 As[2][64 * SA];
    __shared__ __align__(16) __nv_bfloat16 Bs[2][128 * SA];
    int cnt  = min(g_counter, CAP);
    int row0 = blockIdx.x * 64;
    if (row0 >= cnt) return;
    int t = threadIdx.x;
    int lane = t & 31, wid = t >> 5;
    int wm = (wid & 1) * 32;     // warp row base in tile
    int wn = (wid >> 1) * 32;    // warp col base
    int gr4 = lane >> 2;         // fragment row/col group
    int kc  = (lane & 3) * 2;    // fragment k pair

    float acc[2][4][4];
#pragma unroll
    for (int mt = 0; mt < 2; mt++)
#pragma unroll
        for (int nt = 0; nt < 4; nt++)
#pragma unroll
            for (int j = 0; j < 4; j++) acc[mt][nt][j] = 0.f;

    for (int c = 0; c < KC / 32; c++) {
        // stage A hi/lo (64 rows x 32 k): one uint4 (8 bf16) per thread per plane
        {
            int row = t >> 2, q = t & 3;
            int gr = row0 + row;
            uint4 vh = make_uint4(0u, 0u, 0u, 0u), vl = vh;
            if (gr < cnt) {
                size_t s = (size_t)gr * KC + c * 32 + q * 8;
                vh = *(const uint4*)&g_Ahi[s];
                vl = *(const uint4*)&g_Alo[s];
            }
            *(uint4*)&As[0][row * SA + q * 8] = vh;
            *(uint4*)&As[1][row * SA + q * 8] = vl;
        }
        // stage B hi/lo (128 cols x 32 k): two uint4 per thread per plane
#pragma unroll
        for (int q2 = 0; q2 < 2; q2++) {
            int idx = t + q2 * 256;
            int h = idx >> 2, q = idx & 3;
            size_t s = (size_t)h * KC + c * 32 + q * 8;
            *(uint4*)&Bs[0][h * SA + q * 8] = *(const uint4*)&g_Bhi[s];
            *(uint4*)&Bs[1][h * SA + q * 8] = *(const uint4*)&g_Blo[s];
        }
        __syncthreads();

#pragma unroll
        for (int ks = 0; ks < 32; ks += 16) {
            unsigned ah[2][4], al[2][4], bh[4][2], bl[4][2];
#pragma unroll
            for (int mt = 0; mt < 2; mt++) {
                int r0 = wm + mt * 16 + gr4;
                ah[mt][0] = *(const unsigned*)&As[0][(r0    ) * SA + ks + kc];
                ah[mt][1] = *(const unsigned*)&As[0][(r0 + 8) * SA + ks + kc];
                ah[mt][2] = *(const unsigned*)&As[0][(r0    ) * SA + ks + kc + 8];
                ah[mt][3] = *(const unsigned*)&As[0][(r0 + 8) * SA + ks + kc + 8];
                al[mt][0] = *(const unsigned*)&As[1][(r0    ) * SA + ks + kc];
                al[mt][1] = *(const unsigned*)&As[1][(r0 + 8) * SA + ks + kc];
                al[mt][2] = *(const unsigned*)&As[1][(r0    ) * SA + ks + kc + 8];
                al[mt][3] = *(const unsigned*)&As[1][(r0 + 8) * SA + ks + kc + 8];
            }
#pragma unroll
            for (int nt = 0; nt < 4; nt++) {
                int n0 = wn + nt * 8 + gr4;
                bh[nt][0] = *(const unsigned*)&Bs[0][n0 * SA + ks + kc];
                bh[nt][1] = *(const unsigned*)&Bs[0][n0 * SA + ks + kc + 8];
                bl[nt][0] = *(const unsigned*)&Bs[1][n0 * SA + ks + kc];
                bl[nt][1] = *(const unsigned*)&Bs[1][n0 * SA + ks + kc + 8];
            }
#pragma unroll
            for (int mt = 0; mt < 2; mt++)
#pragma unroll
                for (int nt = 0; nt < 4; nt++) {
                    MMA16816(acc[mt][nt], ah[mt], bh[nt]);
                    MMA16816(acc[mt][nt], al[mt], bh[nt]);
                    MMA16816(acc[mt][nt], ah[mt], bl[nt]);
                }
        }
        __syncthreads();
    }

    // epilogue: bias + relu, direct stores (c-frag layout)
#pragma unroll
    for (int mt = 0; mt < 2; mt++) {
#pragma unroll
        for (int nt = 0; nt < 4; nt++) {
            int col = wn + nt * 8 + kc;
            float b0 = b1[col], b1v = b1[col + 1];
            int r0 = row0 + wm + mt * 16 + gr4;
            int r1 = r0 + 8;
            if (r0 < cnt) {
                float2 o;
                o.x = fmaxf(acc[mt][nt][0] + b0, 0.f);
                o.y = fmaxf(acc[mt][nt][1] + b1v, 0.f);
                *(float2*)&g_h[(size_t)r0 * 128 + col] = o;
            }
            if (r1 < cnt) {
                float2 o;
                o.x = fmaxf(acc[mt][nt][2] + b0, 0.f);
                o.y = fmaxf(acc[mt][nt][3] + b1v, 0.f);
                *(float2*)&g_h[(size_t)r1 * 128 + col] = o;
            }
        }
    }
}

// -------------------------------- layer-2 (256 pooled rows) + weighting
__global__ void __launch_bounds__(256) k_pool(const float* __restrict__ x,
                                              const int* __restrict__ pool,
                                              const int* __restrict__ ei,
                                              const float* __restrict__ W2,
                                              const float* __restrict__ root2,
                                              const float* __restrict__ b2) {
    __shared__ float cs[KC];
    __shared__ float red[256];
    const float4* h4 = (const float4*)g_h;
    int p = pool[blockIdx.x];
    int t = threadIdx.x;
    int lane = t & 31, w = t >> 5;

    {
        int r = w;
        int ptr = g_head[r * NN + p];
        int c = 0;
        float4 acc = make_float4(0.f, 0.f, 0.f, 0.f);
        while (ptr >= 0) {
            int src = ei[ptr];
            int ci = g_cid[src];
            float4 hv = h4[ci * 32 + lane];
            acc.x += hv.x; acc.y += hv.y; acc.z += hv.z; acc.w += hv.w;
            c++;
            ptr = g_next[ptr];
        }
        if (c > 1) {
            float s = 1.0f / (float)c;
            acc.x *= s; acc.y *= s; acc.z *= s; acc.w *= s;
        }
        *(float4*)&cs[r * 128 + lane * 4] = acc;
    }
    if (t < 128) {
        int cp = g_cid[p];
        cs[1024 + t] = g_h[(size_t)cp * 128 + t];
    }
    __syncthreads();

    int j = t & 63, q = t >> 6;
    float s = 0.f;
    int k0 = q * 288;
#pragma unroll 4
    for (int k = k0; k < k0 + 288; k++) {
        float wv = (k < 1024) ? W2[k * 64 + j] : root2[(k - 1024) * 64 + j];
        s += cs[k] * wv;
    }
    red[t] = s;
    __syncthreads();
    if (t < 64) {
        float o = red[t] + red[t + 64] + red[t + 128] + red[t + 192] + b2[j];
        float wp = 4.f * x[p * 128 + 0] + x[p * 128 + 1] + 2.f * x[p * 128 + 2];
        g_part[blockIdx.x * 64 + j] = o * wp;
        if (j == 0) g_wp[blockIdx.x] = wp;
    }
}

__global__ void k_final(float* __restrict__ out) {
    int j = threadIdx.x;   // 64
    float acc = 0.f;
    for (int i = 0; i < NP; i++) acc += g_part[i * 64 + j];
    float ws = 0.f;
    for (int i = 0; i < NP; i++) ws += g_wp[i];
    out[j] = acc / (ws + 1e-9f);
}

// ---------------------------------------------------------------- launch
extern "C" void kernel_launch(void* const* d_in, const int* in_sizes, int n_in,
                              void* d_out, int out_size) {
    const float* x     = (const float*)d_in[0];
    const int*   ei    = (const int*)  d_in[1];
    const int*   et    = (const int*)  d_in[2];
    const int*   pool  = (const int*)  d_in[3];
    const float* W1    = (const float*)d_in[4];
    const float* root1 = (const float*)d_in[5];
    const float* b1    = (const float*)d_in[6];
    const float* W2    = (const float*)d_in[7];
    const float* root2 = (const float*)d_in[8];
    const float* b2    = (const float*)d_in[9];
    float* out = (float*)d_out;
    (void)in_sizes; (void)n_in; (void)out_size;

    k_init     <<<(NR * NN + 255) / 256, 256>>>();
    k_mark_pool<<<1, NP>>>(pool);
    k_mark_src <<<(NE + 255) / 256, 256>>>(ei);
    k_compact  <<<(NN + 255) / 256, 256>>>();
    k_build    <<<(NE + 255) / 256, 256>>>(ei, et);
    k_wsplit   <<<(128 * KC + 255) / 256, 256>>>(W1, root1);
    k_agg1     <<<2048, 256>>>(x, ei);
    k_gemm1h   <<<CAP / 64, 256>>>(b1);
    k_pool     <<<NP, 256>>>(x, pool, ei, W2, root2, b2);
    k_final    <<<1, 64>>>(out);
}

// round 8
// speedup vs baseline: 3.0338x; 1.0397x over previous
#include <cuda_runtime.h>
#include <cuda_bf16.h>

#define NN   50000
#define NE   1600000
#define NR   8
#define KC   1152        // NR*128 + 128
#define CAP  16384
#define NP   256
#define DOUT 64

// ---- scratch (zero-initialized once by CUDA) ----
__device__ int   g_pmap[NN];          // 1 = pooled dst (idempotent across runs)
__device__ int   g_nf[NN];            // 1 = needed node (idempotent across runs)
__device__ int   g_cid[NN];
__device__ int   g_nodes[CAP];
__device__ int   g_counter;           // reset each run in k_mark_pool
__device__ unsigned g_done;           // pool-block ticket; last block resets to 0
__device__ int   g_head[NR * NN];     // head = edge+1, 0 = empty; CLEARED each run
__device__ int   g_next[NE];          // next pointer (edge+1 or 0), rewritten each run
__device__ __align__(16) __nv_bfloat16 g_Ahi[(size_t)CAP * KC];
__device__ __align__(16) __nv_bfloat16 g_Alo[(size_t)CAP * KC];
__device__ __align__(16) __nv_bfloat16 g_Bhi[128 * KC];   // [outcol h][k]
__device__ __align__(16) __nv_bfloat16 g_Blo[128 * KC];
__device__ float g_h[(size_t)CAP * 128];
__device__ float g_part[NP * DOUT];
__device__ float g_wp[NP];

static __device__ __forceinline__ void split2(float v, __nv_bfloat16& hi, __nv_bfloat16& lo) {
    hi = __float2bfloat16_rn(v);
    lo = __float2bfloat16_rn(v - __bfloat162float(hi));
}

// warp mma m16n8k16 bf16 -> f32 accum (baseline PTX, HMMA on sm_103)
#define MMA16816(c, a, b) \
    asm volatile("mma.sync.aligned.m16n8k16.row.col.f32.bf16.bf16.f32 " \
                 "{%0,%1,%2,%3},{%4,%5,%6,%7},{%8,%9},{%0,%1,%2,%3};" \
                 : "+f"((c)[0]), "+f"((c)[1]), "+f"((c)[2]), "+f"((c)[3]) \
                 : "r"((a)[0]), "r"((a)[1]), "r"((a)[2]), "r"((a)[3]), \
                   "r"((b)[0]), "r"((b)[1]))

// ------------------------------------------- kernel 1: mark pool + resets
__global__ void k_mark_pool(const int* __restrict__ pool) {
    int p = pool[threadIdx.x];
    g_pmap[p] = 1;
    g_nf[p]   = 1;
    if (threadIdx.x == 0) { g_counter = 0; g_done = 0; }
}

// --------------------- kernel 2: mark_src || wsplit || head-clear
#define NB_MS ((NE + 255) / 256)
#define NB_WS ((128 * KC + 255) / 256)
#define NB_HC ((NR * NN / 4 + 255) / 256)    // clear as int4
__global__ void k_mark_ws(const int* __restrict__ ei,
                          const float* __restrict__ W1,
                          const float* __restrict__ root1) {
    int b = blockIdx.x;
    if (b < NB_MS) {
        int e = b * 256 + threadIdx.x;
        if (e < NE) {
            int dst = ei[NE + e];
            if (g_pmap[dst]) g_nf[ei[e]] = 1;
        }
    } else if (b < NB_MS + NB_WS) {
        int idx = (b - NB_MS) * 256 + threadIdx.x;   // 128*KC
        if (idx < 128 * KC) {
            int h = idx / KC, k = idx - h * KC;
            float w = (k < 1024) ? W1[k * 128 + h] : root1[(k - 1024) * 128 + h];
            __nv_bfloat16 hi, lo;
            split2(w, hi, lo);
            g_Bhi[idx] = hi;
            g_Blo[idx] = lo;
        }
    } else {
        int idx = (b - NB_MS - NB_WS) * 256 + threadIdx.x;   // int4 index
        if (idx < NR * NN / 4)
            ((int4*)g_head)[idx] = make_int4(0, 0, 0, 0);
    }
}

// ------------------------------------------- kernel 3: compact || build
#define NB_CP ((NN + 255) / 256)
__global__ void k_cb(const int* __restrict__ ei, const int* __restrict__ et) {
    int b = blockIdx.x;
    if (b < NB_CP) {
        int v = b * 256 + threadIdx.x;
        int lane = threadIdx.x & 31;
        int pred = (v < NN) && g_nf[v];
        unsigned mask = __ballot_sync(0xFFFFFFFF, pred);
        if (mask) {
            int leader = __ffs(mask) - 1;
            int base = 0;
            if (lane == leader) base = atomicAdd(&g_counter, __popc(mask));
            base = __shfl_sync(0xFFFFFFFF, base, leader);
            if (pred) {
                int c = base + __popc(mask & ((1u << lane) - 1));
                if (c < CAP) { g_cid[v] = c; g_nodes[c] = v; }
            }
        }
    } else {
        int e = (b - NB_CP) * 256 + threadIdx.x;
        if (e < NE) {
            int dst = ei[NE + e];
            if (g_nf[dst]) {
                int r = et[e];
                g_next[e] = atomicExch(&g_head[r * NN + dst], e + 1);
            }
        }
    }
}

// ------------------------------------------- kernel 4: layer-1 aggregation
__global__ void k_agg1(const float* __restrict__ x, const int* __restrict__ ei) {
    const float4* x4 = (const float4*)x;
    int wid   = (blockIdx.x * blockDim.x + threadIdx.x) >> 5;
    int lane  = threadIdx.x & 31;
    int nwarp = (gridDim.x * blockDim.x) >> 5;
    int cnt   = min(g_counter, CAP);
    int ntask = cnt * 9;
    for (int t = wid; t < ntask; t += nwarp) {
        int i = t / 9;
        int r = t - i * 9;
        int v = g_nodes[i];
        float4 acc = make_float4(0.f, 0.f, 0.f, 0.f);
        if (r == 8) {
            acc = x4[v * 32 + lane];
        } else {
            int ptr = g_head[r * NN + v];
            int c = 0;
            while (ptr) {
                int e = ptr - 1;
                int src = ei[e];
                float4 xv = x4[src * 32 + lane];
                acc.x += xv.x; acc.y += xv.y; acc.z += xv.z; acc.w += xv.w;
                c++;
                ptr = g_next[e];
            }
            if (c > 1) {
                float s = 1.0f / (float)c;
                acc.x *= s; acc.y *= s; acc.z *= s; acc.w *= s;
            }
        }
        __nv_bfloat16 h[4], l[4];
        split2(acc.x, h[0], l[0]);
        split2(acc.y, h[1], l[1]);
        split2(acc.z, h[2], l[2]);
        split2(acc.w, h[3], l[3]);
        size_t off = (size_t)i * KC + r * 128 + lane * 4;
        *(uint2*)&g_Ahi[off] = *(uint2*)h;
        *(uint2*)&g_Alo[off] = *(uint2*)l;
    }
}

// ------------------------------------------- kernel 5: layer-1 GEMM (HMMA)
#define SA 40
__global__ void __launch_bounds__(256) k_gemm1h(const float* __restrict__ b1) {
    __shared__ __align__(16) __nv_bfloat16 As[2][64 * SA];
    __shared__ __align__(16) __nv_bfloat16 Bs[2][128 * SA];
    int cnt  = min(g_counter, CAP);
    int row0 = blockIdx.x * 64;
    if (row0 >= cnt) return;
    int t = threadIdx.x;
    int lane = t & 31, wid = t >> 5;
    int wm = (wid & 1) * 32;
    int wn = (wid >> 1) * 32;
    int gr4 = lane >> 2;
    int kc  = (lane & 3) * 2;

    float acc[2][4][4];
#pragma unroll
    for (int mt = 0; mt < 2; mt++)
#pragma unroll
        for (int nt = 0; nt < 4; nt++)
#pragma unroll
            for (int j = 0; j < 4; j++) acc[mt][nt][j] = 0.f;

    for (int c = 0; c < KC / 32; c++) {
        {
            int row = t >> 2, q = t & 3;
            int gr = row0 + row;
            uint4 vh = make_uint4(0u, 0u, 0u, 0u), vl = vh;
            if (gr < cnt) {
                size_t s = (size_t)gr * KC + c * 32 + q * 8;
                vh = *(const uint4*)&g_Ahi[s];
                vl = *(const uint4*)&g_Alo[s];
            }
            *(uint4*)&As[0][row * SA + q * 8] = vh;
            *(uint4*)&As[1][row * SA + q * 8] = vl;
        }
#pragma unroll
        for (int q2 = 0; q2 < 2; q2++) {
            int idx = t + q2 * 256;
            int h = idx >> 2, q = idx & 3;
            size_t s = (size_t)h * KC + c * 32 + q * 8;
            *(uint4*)&Bs[0][h * SA + q * 8] = *(const uint4*)&g_Bhi[s];
            *(uint4*)&Bs[1][h * SA + q * 8] = *(const uint4*)&g_Blo[s];
        }
        __syncthreads();

#pragma unroll
        for (int ks = 0; ks < 32; ks += 16) {
            unsigned ah[2][4], al[2][4], bh[4][2], bl[4][2];
#pragma unroll
            for (int mt = 0; mt < 2; mt++) {
                int r0 = wm + mt * 16 + gr4;
                ah[mt][0] = *(const unsigned*)&As[0][(r0    ) * SA + ks + kc];
                ah[mt][1] = *(const unsigned*)&As[0][(r0 + 8) * SA + ks + kc];
                ah[mt][2] = *(const unsigned*)&As[0][(r0    ) * SA + ks + kc + 8];
                ah[mt][3] = *(const unsigned*)&As[0][(r0 + 8) * SA + ks + kc + 8];
                al[mt][0] = *(const unsigned*)&As[1][(r0    ) * SA + ks + kc];
                al[mt][1] = *(const unsigned*)&As[1][(r0 + 8) * SA + ks + kc];
                al[mt][2] = *(const unsigned*)&As[1][(r0    ) * SA + ks + kc + 8];
                al[mt][3] = *(const unsigned*)&As[1][(r0 + 8) * SA + ks + kc + 8];
            }
#pragma unroll
            for (int nt = 0; nt < 4; nt++) {
                int n0 = wn + nt * 8 + gr4;
                bh[nt][0] = *(const unsigned*)&Bs[0][n0 * SA + ks + kc];
                bh[nt][1] = *(const unsigned*)&Bs[0][n0 * SA + ks + kc + 8];
                bl[nt][0] = *(const unsigned*)&Bs[1][n0 * SA + ks + kc];
                bl[nt][1] = *(const unsigned*)&Bs[1][n0 * SA + ks + kc + 8];
            }
#pragma unroll
            for (int mt = 0; mt < 2; mt++)
#pragma unroll
                for (int nt = 0; nt < 4; nt++) {
                    MMA16816(acc[mt][nt], ah[mt], bh[nt]);
                    MMA16816(acc[mt][nt], al[mt], bh[nt]);
                    MMA16816(acc[mt][nt], ah[mt], bl[nt]);
                }
        }
        __syncthreads();
    }

#pragma unroll
    for (int mt = 0; mt < 2; mt++) {
#pragma unroll
        for (int nt = 0; nt < 4; nt++) {
            int col = wn + nt * 8 + kc;
            float b0 = b1[col], b1v = b1[col + 1];
            int r0 = row0 + wm + mt * 16 + gr4;
            int r1 = r0 + 8;
            if (r0 < cnt) {
                float2 o;
                o.x = fmaxf(acc[mt][nt][0] + b0, 0.f);
                o.y = fmaxf(acc[mt][nt][1] + b1v, 0.f);
                *(float2*)&g_h[(size_t)r0 * 128 + col] = o;
            }
            if (r1 < cnt) {
                float2 o;
                o.x = fmaxf(acc[mt][nt][2] + b0, 0.f);
                o.y = fmaxf(acc[mt][nt][3] + b1v, 0.f);
                *(float2*)&g_h[(size_t)r1 * 128 + col] = o;
            }
        }
    }
}

// ------------------------------------------- kernel 6: layer-2 + pool + final
__global__ void __launch_bounds__(256) k_pool(const float* __restrict__ x,
                                              const int* __restrict__ pool,
                                              const int* __restrict__ ei,
                                              const float* __restrict__ W2,
                                              const float* __restrict__ root2,
                                              const float* __restrict__ b2,
                                              float* __restrict__ out) {
    __shared__ float cs[KC];
    __shared__ float red[256];
    __shared__ unsigned s_ticket;
    const float4* h4 = (const float4*)g_h;
    int p = pool[blockIdx.x];
    int t = threadIdx.x;
    int lane = t & 31, w = t >> 5;

    {
        int r = w;
        int ptr = g_head[r * NN + p];
        int c = 0;
        float4 acc = make_float4(0.f, 0.f, 0.f, 0.f);
        while (ptr) {
            int e = ptr - 1;
            int src = ei[e];
            int ci = g_cid[src];
            float4 hv = h4[ci * 32 + lane];
            acc.x += hv.x; acc.y += hv.y; acc.z += hv.z; acc.w += hv.w;
            c++;
            ptr = g_next[e];
        }
        if (c > 1) {
            float s = 1.0f / (float)c;
            acc.x *= s; acc.y *= s; acc.z *= s; acc.w *= s;
        }
        *(float4*)&cs[r * 128 + lane * 4] = acc;
    }
    if (t < 128) {
        int cp = g_cid[p];
        cs[1024 + t] = g_h[(size_t)cp * 128 + t];
    }
    __syncthreads();

    int j = t & 63, q = t >> 6;
    float s = 0.f;
    int k0 = q * 288;
#pragma unroll 4
    for (int k = k0; k < k0 + 288; k++) {
        float wv = (k < 1024) ? W2[k * 64 + j] : root2[(k - 1024) * 64 + j];
        s += cs[k] * wv;
    }
    red[t] = s;
    __syncthreads();
    if (t < 64) {
        float o = red[t] + red[t + 64] + red[t + 128] + red[t + 192] + b2[j];
        float wp = 4.f * x[p * 128 + 0] + x[p * 128 + 1] + 2.f * x[p * 128 + 2];
        g_part[blockIdx.x * 64 + j] = o * wp;
        if (j == 0) g_wp[blockIdx.x] = wp;
    }

    // ---- last-block final reduction ----
    __threadfence();
    __syncthreads();
    if (t == 0) s_ticket = atomicAdd(&g_done, 1);
    __syncthreads();
    if (s_ticket == NP - 1) {
        __threadfence();
        if (t < 64) {
            float acc = 0.f;
            for (int i = 0; i < NP; i++) acc += g_part[i * 64 + t];
            float ws = 0.f;
            for (int i = 0; i < NP; i++) ws += g_wp[i];
            out[t] = acc / (ws + 1e-9f);
        }
        if (t == 0) g_done = 0;   // reset for next replay
    }
}

// ---------------------------------------------------------------- launch
extern "C" void kernel_launch(void* const* d_in, const int* in_sizes, int n_in,
                              void* d_out, int out_size) {
    const float* x     = (const float*)d_in[0];
    const int*   ei    = (const int*)  d_in[1];
    const int*   et    = (const int*)  d_in[2];
    const int*   pool  = (const int*)  d_in[3];
    const float* W1    = (const float*)d_in[4];
    const float* root1 = (const float*)d_in[5];
    const float* b1    = (const float*)d_in[6];
    const float* W2    = (const float*)d_in[7];
    const float* root2 = (const float*)d_in[8];
    const float* b2    = (const float*)d_in[9];
    float* out = (float*)d_out;
    (void)in_sizes; (void)n_in; (void)out_size;

    k_mark_pool<<<1, NP>>>(pool);
    k_mark_ws  <<<NB_MS + NB_WS + NB_HC, 256>>>(ei, W1, root1);
    k_cb       <<<NB_CP + NB_MS, 256>>>(ei, et);
    k_agg1     <<<2048, 256>>>(x, ei);
    k_gemm1h   <<<CAP / 64, 256>>>(b1);
    k_pool     <<<NP, 256>>>(x, pool, ei, W2, root2, b2, out);
}